// round 15
// baseline (speedup 1.0000x reference)
#include <cuda_runtime.h>
#include <cuda_fp16.h>
#include <cstdint>

#define DI __device__ __forceinline__

static constexpr int HDIM   = 1024;
static constexpr int BATCH  = 8192;
static constexpr int BM     = 128;   // batch rows per CTA
static constexpr int BN     = 32;    // gate cols per CTA
static constexpr int NTH    = 256;   // 8 warps: 4 (m) x 2 (n)
static constexpr int NSTAGE = 48;    // 16 att + 16 input + 16 hx K=64-stages
static constexpr int RING   = 3;     // 3-deep ring -> 96KB -> 2 CTAs/SM

// K=64 fp16 stage buffer: A 128x64 (16KB) + B 4x32x64 (16KB); 128B rows
static constexpr int ABYTES = BM * 128;        // 16384
static constexpr int BUFB   = ABYTES + 16384;  // 32768
static constexpr int SMEMB  = RING * BUFB;     // 98304

// fp16 scratch (u32 element offsets; 2 halves per u32)
static constexpr size_t OFF_ATT  = 0;
static constexpr size_t OFF_INP  = 4194304;
static constexpr size_t OFF_HX   = 8388608;
static constexpr size_t OFF_WATT = 12582912;
static constexpr size_t OFF_WIH  = 13631488;
static constexpr size_t OFF_WHH  = 15728640;
static constexpr size_t CVT_TOTAL = 17825792;   // ~71.3 MB

__device__ uint32_t g_cvt[CVT_TOTAL];

DI float sigmf(float x) { return 1.0f / (1.0f + __expf(-x)); }

DI uint32_t smem_u32(const void* p) {
    uint32_t r;
    asm("{ .reg .u64 t; cvta.to.shared.u64 t, %1; cvt.u32.u64 %0, t; }" : "=r"(r) : "l"(p));
    return r;
}
DI void cp16(uint32_t sdst, const uint32_t* gsrc) {
    asm volatile("cp.async.cg.shared.global [%0], [%1], 16;" :: "r"(sdst), "l"(gsrc));
}
DI void cp_commit() { asm volatile("cp.async.commit_group;" ::: "memory"); }
template <int N>
DI void cp_wait() { asm volatile("cp.async.wait_group %0;" :: "n"(N) : "memory"); }

DI void ldsm4(uint32_t* r, uint32_t addr) {
    asm volatile("ldmatrix.sync.aligned.m8n8.x4.shared.b16 {%0,%1,%2,%3}, [%4];"
                 : "=r"(r[0]), "=r"(r[1]), "=r"(r[2]), "=r"(r[3]) : "r"(addr));
}
DI void mma16(float* d, const uint32_t* a, const uint32_t* b) {
    asm volatile(
        "mma.sync.aligned.m16n8k16.row.col.f32.f16.f16.f32 "
        "{%0,%1,%2,%3}, {%4,%5,%6,%7}, {%8,%9}, {%0,%1,%2,%3};"
        : "+f"(d[0]), "+f"(d[1]), "+f"(d[2]), "+f"(d[3])
        : "r"(a[0]), "r"(a[1]), "r"(a[2]), "r"(a[3]), "r"(b[0]), "r"(b[1]));
}

// ---- prepass: fp32 -> fp16(RN), full-width uint4 stores (6 segments, 1 launch) ----
__global__ void cvt_all_kernel(const float4* s_att, const float4* s_inp, const float4* s_hx,
                               const float4* s_watt, const float4* s_wih, const float4* s_whh)
{
    const int seg = blockIdx.y;
    const float4* src;
    uint4* dst;
    int n16;                               // count of 16-byte fp16 output chunks
    uint32_t* g = g_cvt;
    switch (seg) {
        case 0: src = s_att;  dst = (uint4*)(g + OFF_ATT);  n16 = 1048576; break;
        case 1: src = s_inp;  dst = (uint4*)(g + OFF_INP);  n16 = 1048576; break;
        case 2: src = s_hx;   dst = (uint4*)(g + OFF_HX);   n16 = 1048576; break;
        case 3: src = s_watt; dst = (uint4*)(g + OFF_WATT); n16 = 262144;  break;
        case 4: src = s_wih;  dst = (uint4*)(g + OFF_WIH);  n16 = 524288;  break;
        default: src = s_whh; dst = (uint4*)(g + OFF_WHH);  n16 = 524288;  break;
    }
    int i = blockIdx.x * blockDim.x + threadIdx.x;
    const int stride = gridDim.x * blockDim.x;
    for (; i < n16; i += stride) {
        float4 v0 = __ldg(src + 2 * i);
        float4 v1 = __ldg(src + 2 * i + 1);
        __half2 h0 = __float22half2_rn(make_float2(v0.x, v0.y));
        __half2 h1 = __float22half2_rn(make_float2(v0.z, v0.w));
        __half2 h2 = __float22half2_rn(make_float2(v1.x, v1.y));
        __half2 h3 = __float22half2_rn(make_float2(v1.z, v1.w));
        dst[i] = make_uint4(*(const uint32_t*)&h0, *(const uint32_t*)&h1,
                            *(const uint32_t*)&h2, *(const uint32_t*)&h3);
    }
}

// ---- main kernel ----
// stages 0..15 : A=att,   B=watt (2 att blocks)
// stages 16..31: A=input, B=wih  (4 gate blocks)
// stages 32..47: A=hx,    B=whh  (4 gate blocks)
DI void issue_stage(int s, uint32_t buf, uint32_t sA, uint32_t sB,
                    const uint32_t* Arow, const uint32_t* Brow)
{
    const int seg = s >> 4;
    const int k0  = (s & 15) << 5;                 // u32 offset within 512-u32 row
    const uint32_t bsel = (seg == 0) ? 0u : ((seg == 1) ? 1048576u : 3145728u);
    const uint32_t* Ap = Arow + (size_t)seg * 4194304 + k0;
    const uint32_t* Bp = Brow + bsel + k0;
    const uint32_t dA = buf + sA;
    const uint32_t dB = buf + sB;
    cp16(dA,         Ap);                // rows 0-31
    cp16(dA + 4096,  Ap + 16384);        // rows 32-63
    cp16(dA + 8192,  Ap + 32768);        // rows 64-95
    cp16(dA + 12288, Ap + 49152);        // rows 96-127
    cp16(dB,         Bp);                // gate block 0
    cp16(dB + 4096,  Bp + 524288);       // gate block 1
    if (seg != 0) {
        cp16(dB + 8192,  Bp + 1048576);  // gate block 2
        cp16(dB + 12288, Bp + 1572864);  // gate block 3
    }
    cp_commit();
}

// XOR-then-add addressing: kx only touches bits 5-6; all block offsets are
// >= bit 11, so (base ^ kx) + off is bit-identical to (base + off) ^ kx while
// letting ptxas fold the adds into LDSM immediate offsets (2 LOP3/k16, not 6).
template <int NB>
DI void compute_stage(uint32_t buf, uint32_t pA0, uint32_t pB,
                      float c[][2][2][4])
{
    const uint32_t aBase = buf + pA0;
    const uint32_t bBase = buf + pB;
    #pragma unroll
    for (int k16 = 0; k16 < 4; ++k16) {
        const uint32_t kx = (uint32_t)(k16 << 5);
        const uint32_t aX = aBase ^ kx;
        const uint32_t bX = bBase ^ kx;
        uint32_t a0[4], a1[4];
        ldsm4(a0, aX);
        ldsm4(a1, aX + 2048);           // rows +16: same swizzle bits
        #pragma unroll
        for (int blk = 0; blk < NB; ++blk) {
            uint32_t b[4];
            ldsm4(b, bX + blk * 4096);
            mma16(c[blk][0][0], a0, b);
            mma16(c[blk][0][1], a0, b + 2);
            mma16(c[blk][1][0], a1, b);
            mma16(c[blk][1][1], a1, b + 2);
        }
    }
}

__global__ __launch_bounds__(NTH, 2)
void lstm_att_kernel(const float* __restrict__ cx,
                     const float* __restrict__ bih, const float* __restrict__ bhh,
                     const float* __restrict__ batt,
                     float* __restrict__ out)
{
    extern __shared__ char smem[];
    const int tid  = threadIdx.x;
    const int wid  = tid >> 5;
    const int lane = tid & 31;
    const int wm = wid >> 1, wn = wid & 1;
    const int n0 = blockIdx.x * BN;
    const int m0 = blockIdx.y * BM;
    const uint32_t sbase = smem_u32(smem);

    // ---- producer addressing (128B rows, chunk ^ row&7 swizzle) ----
    const int tid8 = tid >> 3;
    const int cc   = tid & 7;
    const uint32_t sw   = (uint32_t)((cc ^ (tid8 & 7)) << 4);
    const uint32_t sAof = (uint32_t)(tid8 * 128) + sw;
    const uint32_t sBof = (uint32_t)ABYTES + (uint32_t)(tid8 * 128) + sw;
    const uint32_t* Arow = g_cvt + OFF_ATT  + (size_t)(m0 + tid8) * 512 + cc * 4;
    const uint32_t* Brow = g_cvt + OFF_WATT + (size_t)(n0 + tid8) * 512 + cc * 4;

    // ---- consumer (ldsm) addressing, XOR-folded ----
    const int arow = wm * 32 + (lane & 15);
    const int ahi  = (lane >> 4) & 1;
    const int ax   = arow & 7;
    const uint32_t pA0 = (uint32_t)(arow * 128) ^ (uint32_t)(((ahi ^ ax) & 7) << 4);
    const int brow = wn * 16 + (lane & 7) + ((lane & 16) >> 1);
    const int bhi  = (lane >> 3) & 1;
    const int bx   = brow & 7;
    const uint32_t pB  = (uint32_t)ABYTES + ((uint32_t)(brow * 128) ^ (uint32_t)(((bhi ^ bx) & 7) << 4));

    issue_stage(0, sbase,        sAof, sBof, Arow, Brow);
    issue_stage(1, sbase + BUFB, sAof, sBof, Arow, Brow);

    int ring_c = 0, ring_i = 2;

    // ===== phase 1: att segment (stages 0..15), 32 accum regs =====
    float ca[2][2][2][4];
    #pragma unroll
    for (int b = 0; b < 2; ++b)
        #pragma unroll
        for (int mf = 0; mf < 2; ++mf)
            #pragma unroll
            for (int nf = 0; nf < 2; ++nf)
                #pragma unroll
                for (int i = 0; i < 4; ++i) ca[b][mf][nf][i] = 0.0f;

    for (int s = 0; s < 16; ++s) {
        cp_wait<1>();
        __syncthreads();
        // compute FIRST: first ldsm isn't queued behind 8 cp.asyncs in the LSU
        compute_stage<2>(sbase + ring_c * BUFB, pA0, pB, ca);
        issue_stage(s + 2, sbase + ring_i * BUFB, sAof, sBof, Arow, Brow);
        ring_c = (ring_c == RING - 1) ? 0 : ring_c + 1;
        ring_i = (ring_i == RING - 1) ? 0 : ring_i + 1;
    }

    // ---- collapse att gates to 16 partials: p = sigmoid(ia) * tanh(aa) ----
    const int gid = lane >> 2, tig = lane & 3;
    float p[2][2][4];
    {
        float bt0[2][2], bt1[2][2];
        #pragma unroll
        for (int nf = 0; nf < 2; ++nf) {
            const int col = n0 + wn * 16 + nf * 8 + tig * 2;
            float2 t0 = __ldg((const float2*)(batt + col));
            float2 t1 = __ldg((const float2*)(batt + 1024 + col));
            bt0[nf][0] = t0.x; bt0[nf][1] = t0.y;
            bt1[nf][0] = t1.x; bt1[nf][1] = t1.y;
        }
        #pragma unroll
        for (int mf = 0; mf < 2; ++mf)
            #pragma unroll
            for (int nf = 0; nf < 2; ++nf)
                #pragma unroll
                for (int i = 0; i < 4; ++i) {
                    const int q = i & 1;
                    float ia = sigmf(ca[0][mf][nf][i] + bt0[nf][q]);
                    float aa = tanhf(ca[1][mf][nf][i] + bt1[nf][q]);
                    p[mf][nf][i] = ia * aa;
                }
    }

    // ===== phase 2: input + hx segments (stages 16..47), 64+16 accum regs =====
    float cm[4][2][2][4];
    #pragma unroll
    for (int b = 0; b < 4; ++b)
        #pragma unroll
        for (int mf = 0; mf < 2; ++mf)
            #pragma unroll
            for (int nf = 0; nf < 2; ++nf)
                #pragma unroll
                for (int i = 0; i < 4; ++i) cm[b][mf][nf][i] = 0.0f;

    for (int s = 16; s < NSTAGE; ++s) {
        cp_wait<1>();
        __syncthreads();
        compute_stage<4>(sbase + ring_c * BUFB, pA0, pB, cm);
        if (s + 2 < NSTAGE)
            issue_stage(s + 2, sbase + ring_i * BUFB, sAof, sBof, Arow, Brow);
        else
            cp_commit();     // keep group accounting so wait<1> retires the tail
        ring_c = (ring_c == RING - 1) ? 0 : ring_c + 1;
        ring_i = (ring_i == RING - 1) ? 0 : ring_i + 1;
    }

    // ---- fused LSTM epilogue ----
    // biases depend only on the column: hoist out of the row loops
    float gb[4][2][2];   // [gate][nf][q] = bih + bhh
    #pragma unroll
    for (int nf = 0; nf < 2; ++nf) {
        const int col = n0 + wn * 16 + nf * 8 + tig * 2;
        #pragma unroll
        for (int g4 = 0; g4 < 4; ++g4) {
            float2 b1 = __ldg((const float2*)(bih + g4 * 1024 + col));
            float2 b2 = __ldg((const float2*)(bhh + g4 * 1024 + col));
            gb[g4][nf][0] = b1.x + b2.x;
            gb[g4][nf][1] = b1.y + b2.y;
        }
    }
    const size_t cy_base = (size_t)BATCH * HDIM;
    #pragma unroll
    for (int mf = 0; mf < 2; ++mf) {
        #pragma unroll
        for (int i2 = 0; i2 < 2; ++i2) {
            const int row = m0 + wm * 32 + mf * 16 + gid + i2 * 8;
            #pragma unroll
            for (int nf = 0; nf < 2; ++nf) {
                const int col = n0 + wn * 16 + nf * 8 + tig * 2;
                float2 cx2 = __ldg((const float2*)(cx + (size_t)row * HDIM + col));
                float hyv[2], cyv[2];
                #pragma unroll
                for (int q = 0; q < 2; ++q) {
                    const int i = i2 * 2 + q;
                    float gi  = cm[0][mf][nf][i] + gb[0][nf][q];
                    float gf  = cm[1][mf][nf][i] + gb[1][nf][q];
                    float gc  = cm[2][mf][nf][i] + gb[2][nf][q];
                    float go  = cm[3][mf][nf][i] + gb[3][nf][q];
                    float i_  = sigmf(gi);
                    float f_  = sigmf(gf);
                    float c_  = tanhf(gc);
                    float o_  = sigmf(go);
                    float cv  = f_ * ((q == 0) ? cx2.x : cx2.y) + i_ * c_ + p[mf][nf][i];
                    cyv[q] = cv;
                    hyv[q] = o_ * tanhf(cv);
                }
                *(float2*)(out + (size_t)row * HDIM + col)           = make_float2(hyv[0], hyv[1]);
                *(float2*)(out + cy_base + (size_t)row * HDIM + col) = make_float2(cyv[0], cyv[1]);
            }
        }
    }
}

extern "C" void kernel_launch(void* const* d_in, const int* in_sizes, int n_in,
                              void* d_out, int out_size)
{
    (void)in_sizes; (void)n_in; (void)out_size;
    const float* inp  = (const float*)d_in[0];
    const float* hx   = (const float*)d_in[1];
    const float* cx   = (const float*)d_in[2];
    const float* att  = (const float*)d_in[3];
    const float* wih  = (const float*)d_in[4];
    const float* whh  = (const float*)d_in[5];
    const float* bih  = (const float*)d_in[6];
    const float* bhh  = (const float*)d_in[7];
    const float* watt = (const float*)d_in[8];
    const float* batt = (const float*)d_in[9];
    float* out = (float*)d_out;

    dim3 cgrid(1024, 6);
    cvt_all_kernel<<<cgrid, 256>>>((const float4*)att, (const float4*)inp,
                                   (const float4*)hx,  (const float4*)watt,
                                   (const float4*)wih, (const float4*)whh);

    cudaFuncSetAttribute(lstm_att_kernel,
                         cudaFuncAttributeMaxDynamicSharedMemorySize, SMEMB);
    dim3 grid(HDIM / BN, BATCH / BM);
    lstm_att_kernel<<<grid, NTH, SMEMB>>>(cx, bih, bhh, batt, out);
}

// round 16
// speedup vs baseline: 1.0238x; 1.0238x over previous
#include <cuda_runtime.h>
#include <cuda_fp16.h>
#include <cstdint>

#define DI __device__ __forceinline__

static constexpr int HDIM   = 1024;
static constexpr int BATCH  = 8192;
static constexpr int BM     = 128;   // batch rows per CTA
static constexpr int BN     = 32;    // gate cols per CTA
static constexpr int NTH    = 256;   // 8 warps: 4 (m) x 2 (n)
static constexpr int NSTAGE = 48;    // 16 att + 16 input + 16 hx K=64-stages
static constexpr int RING   = 3;     // 3-deep ring -> 96KB -> 2 CTAs/SM

// K=64 fp16 stage buffer: A 128x64 (16KB) + B 4x32x64 (16KB); 128B rows
static constexpr int ABYTES = BM * 128;        // 16384
static constexpr int BUFB   = ABYTES + 16384;  // 32768
static constexpr int SMEMB  = RING * BUFB;     // 98304

// fp16 scratch (u32 element offsets; 2 halves per u32)
static constexpr size_t OFF_ATT  = 0;
static constexpr size_t OFF_INP  = 4194304;
static constexpr size_t OFF_HX   = 8388608;
static constexpr size_t OFF_WATT = 12582912;
static constexpr size_t OFF_WIH  = 13631488;
static constexpr size_t OFF_WHH  = 15728640;
static constexpr size_t CVT_TOTAL = 17825792;   // ~71.3 MB

__device__ uint32_t g_cvt[CVT_TOTAL];

DI float sigmf(float x) { return 1.0f / (1.0f + __expf(-x)); }

DI uint32_t smem_u32(const void* p) {
    uint32_t r;
    asm("{ .reg .u64 t; cvta.to.shared.u64 t, %1; cvt.u32.u64 %0, t; }" : "=r"(r) : "l"(p));
    return r;
}
DI void cp16(uint32_t sdst, const uint32_t* gsrc) {
    asm volatile("cp.async.cg.shared.global [%0], [%1], 16;" :: "r"(sdst), "l"(gsrc));
}
DI void cp_commit() { asm volatile("cp.async.commit_group;" ::: "memory"); }
template <int N>
DI void cp_wait() { asm volatile("cp.async.wait_group %0;" :: "n"(N) : "memory"); }

DI void ldsm4(uint32_t* r, uint32_t addr) {
    asm volatile("ldmatrix.sync.aligned.m8n8.x4.shared.b16 {%0,%1,%2,%3}, [%4];"
                 : "=r"(r[0]), "=r"(r[1]), "=r"(r[2]), "=r"(r[3]) : "r"(addr));
}
DI void mma16(float* d, const uint32_t* a, const uint32_t* b) {
    asm volatile(
        "mma.sync.aligned.m16n8k16.row.col.f32.f16.f16.f32 "
        "{%0,%1,%2,%3}, {%4,%5,%6,%7}, {%8,%9}, {%0,%1,%2,%3};"
        : "+f"(d[0]), "+f"(d[1]), "+f"(d[2]), "+f"(d[3])
        : "r"(a[0]), "r"(a[1]), "r"(a[2]), "r"(a[3]), "r"(b[0]), "r"(b[1]));
}

// ---- prepass: fp32 -> fp16(RN), full-width uint4 stores (6 segments, 1 launch) ----
__global__ void cvt_all_kernel(const float4* s_att, const float4* s_inp, const float4* s_hx,
                               const float4* s_watt, const float4* s_wih, const float4* s_whh)
{
    const int seg = blockIdx.y;
    const float4* src;
    uint4* dst;
    int n16;                               // count of 16-byte fp16 output chunks
    uint32_t* g = g_cvt;
    switch (seg) {
        case 0: src = s_att;  dst = (uint4*)(g + OFF_ATT);  n16 = 1048576; break;
        case 1: src = s_inp;  dst = (uint4*)(g + OFF_INP);  n16 = 1048576; break;
        case 2: src = s_hx;   dst = (uint4*)(g + OFF_HX);   n16 = 1048576; break;
        case 3: src = s_watt; dst = (uint4*)(g + OFF_WATT); n16 = 262144;  break;
        case 4: src = s_wih;  dst = (uint4*)(g + OFF_WIH);  n16 = 524288;  break;
        default: src = s_whh; dst = (uint4*)(g + OFF_WHH);  n16 = 524288;  break;
    }
    int i = blockIdx.x * blockDim.x + threadIdx.x;
    const int stride = gridDim.x * blockDim.x;
    for (; i < n16; i += stride) {
        float4 v0 = __ldg(src + 2 * i);
        float4 v1 = __ldg(src + 2 * i + 1);
        __half2 h0 = __float22half2_rn(make_float2(v0.x, v0.y));
        __half2 h1 = __float22half2_rn(make_float2(v0.z, v0.w));
        __half2 h2 = __float22half2_rn(make_float2(v1.x, v1.y));
        __half2 h3 = __float22half2_rn(make_float2(v1.z, v1.w));
        dst[i] = make_uint4(*(const uint32_t*)&h0, *(const uint32_t*)&h1,
                            *(const uint32_t*)&h2, *(const uint32_t*)&h3);
    }
}

// ---- main kernel ----
// stages 0..15 : A=att,   B=watt (2 att blocks)
// stages 16..31: A=input, B=wih  (4 gate blocks)
// stages 32..47: A=hx,    B=whh  (4 gate blocks)
DI void issue_stage(int s, uint32_t buf, uint32_t sA, uint32_t sB,
                    const uint32_t* Arow, const uint32_t* Brow)
{
    const int seg = s >> 4;
    const int k0  = (s & 15) << 5;                 // u32 offset within 512-u32 row
    const uint32_t bsel = (seg == 0) ? 0u : ((seg == 1) ? 1048576u : 3145728u);
    const uint32_t* Ap = Arow + (size_t)seg * 4194304 + k0;
    const uint32_t* Bp = Brow + bsel + k0;
    const uint32_t dA = buf + sA;
    const uint32_t dB = buf + sB;
    cp16(dA,         Ap);                // rows 0-31
    cp16(dA + 4096,  Ap + 16384);        // rows 32-63
    cp16(dA + 8192,  Ap + 32768);        // rows 64-95
    cp16(dA + 12288, Ap + 49152);        // rows 96-127
    cp16(dB,         Bp);                // gate block 0
    cp16(dB + 4096,  Bp + 524288);       // gate block 1
    if (seg != 0) {
        cp16(dB + 8192,  Bp + 1048576);  // gate block 2
        cp16(dB + 12288, Bp + 1572864);  // gate block 3
    }
    cp_commit();
}

template <int NB>
DI void compute_stage(uint32_t buf, uint32_t pA0, uint32_t pA1, uint32_t pB,
                      float c[][2][2][4])
{
    const uint32_t aA0 = buf + pA0;
    const uint32_t aA1 = buf + pA1;
    const uint32_t bB  = buf + pB;
    #pragma unroll
    for (int k16 = 0; k16 < 4; ++k16) {
        const uint32_t kx = (uint32_t)(k16 << 5);
        uint32_t a0[4], a1[4];
        ldsm4(a0, aA0 ^ kx);
        ldsm4(a1, aA1 ^ kx);
        #pragma unroll
        for (int blk = 0; blk < NB; ++blk) {
            uint32_t b[4];
            ldsm4(b, (bB + blk * 4096) ^ kx);
            mma16(c[blk][0][0], a0, b);
            mma16(c[blk][0][1], a0, b + 2);
            mma16(c[blk][1][0], a1, b);
            mma16(c[blk][1][1], a1, b + 2);
        }
    }
}

__global__ __launch_bounds__(NTH, 2)
void lstm_att_kernel(const float* __restrict__ cx,
                     const float* __restrict__ bih, const float* __restrict__ bhh,
                     const float* __restrict__ batt,
                     float* __restrict__ out)
{
    extern __shared__ char smem[];
    const int tid  = threadIdx.x;
    const int wid  = tid >> 5;
    const int lane = tid & 31;
    const int wm = wid >> 1, wn = wid & 1;
    const int n0 = blockIdx.x * BN;
    const int m0 = blockIdx.y * BM;
    const uint32_t sbase = smem_u32(smem);

    // ---- producer addressing (128B rows, chunk ^ row&7 swizzle) ----
    const int tid8 = tid >> 3;
    const int cc   = tid & 7;
    const uint32_t sw   = (uint32_t)((cc ^ (tid8 & 7)) << 4);
    const uint32_t sAof = (uint32_t)(tid8 * 128) + sw;
    const uint32_t sBof = (uint32_t)ABYTES + (uint32_t)(tid8 * 128) + sw;
    const uint32_t* Arow = g_cvt + OFF_ATT  + (size_t)(m0 + tid8) * 512 + cc * 4;
    const uint32_t* Brow = g_cvt + OFF_WATT + (size_t)(n0 + tid8) * 512 + cc * 4;

    // ---- consumer (ldsm) addressing, XOR-folded ----
    const int arow = wm * 32 + (lane & 15);
    const int ahi  = (lane >> 4) & 1;
    const int ax   = arow & 7;
    const uint32_t pA0 = (uint32_t)(arow * 128)        ^ (uint32_t)(((ahi ^ ax) & 7) << 4);
    const uint32_t pA1 = (uint32_t)((arow + 16) * 128) ^ (uint32_t)(((ahi ^ ax) & 7) << 4);
    const int brow = wn * 16 + (lane & 7) + ((lane & 16) >> 1);
    const int bhi  = (lane >> 3) & 1;
    const int bx   = brow & 7;
    const uint32_t pB  = (uint32_t)ABYTES + ((uint32_t)(brow * 128) ^ (uint32_t)(((bhi ^ bx) & 7) << 4));

    issue_stage(0, sbase,        sAof, sBof, Arow, Brow);
    issue_stage(1, sbase + BUFB, sAof, sBof, Arow, Brow);

    int ring_c = 0, ring_i = 2;

    // ===== phase 1: att segment (stages 0..15), 32 accum regs =====
    float ca[2][2][2][4];
    #pragma unroll
    for (int b = 0; b < 2; ++b)
        #pragma unroll
        for (int mf = 0; mf < 2; ++mf)
            #pragma unroll
            for (int nf = 0; nf < 2; ++nf)
                #pragma unroll
                for (int i = 0; i < 4; ++i) ca[b][mf][nf][i] = 0.0f;

    for (int s = 0; s < 16; ++s) {
        cp_wait<1>();
        __syncthreads();
        // compute FIRST: first ldsm isn't queued behind 8 cp.asyncs in the LSU
        compute_stage<2>(sbase + ring_c * BUFB, pA0, pA1, pB, ca);
        issue_stage(s + 2, sbase + ring_i * BUFB, sAof, sBof, Arow, Brow);
        ring_c = (ring_c == RING - 1) ? 0 : ring_c + 1;
        ring_i = (ring_i == RING - 1) ? 0 : ring_i + 1;
    }

    // ---- collapse att gates to 16 partials: p = sigmoid(ia) * tanh(aa) ----
    const int gid = lane >> 2, tig = lane & 3;
    float p[2][2][4];
    {
        float bt0[2][2], bt1[2][2];
        #pragma unroll
        for (int nf = 0; nf < 2; ++nf) {
            const int col = n0 + wn * 16 + nf * 8 + tig * 2;
            float2 t0 = __ldg((const float2*)(batt + col));
            float2 t1 = __ldg((const float2*)(batt + 1024 + col));
            bt0[nf][0] = t0.x; bt0[nf][1] = t0.y;
            bt1[nf][0] = t1.x; bt1[nf][1] = t1.y;
        }
        #pragma unroll
        for (int mf = 0; mf < 2; ++mf)
            #pragma unroll
            for (int nf = 0; nf < 2; ++nf)
                #pragma unroll
                for (int i = 0; i < 4; ++i) {
                    const int q = i & 1;
                    float ia = sigmf(ca[0][mf][nf][i] + bt0[nf][q]);
                    float aa = tanhf(ca[1][mf][nf][i] + bt1[nf][q]);
                    p[mf][nf][i] = ia * aa;
                }
    }

    // ===== phase 2: input + hx segments (stages 16..47), 64+16 accum regs =====
    float cm[4][2][2][4];
    #pragma unroll
    for (int b = 0; b < 4; ++b)
        #pragma unroll
        for (int mf = 0; mf < 2; ++mf)
            #pragma unroll
            for (int nf = 0; nf < 2; ++nf)
                #pragma unroll
                for (int i = 0; i < 4; ++i) cm[b][mf][nf][i] = 0.0f;

    for (int s = 16; s < NSTAGE; ++s) {
        cp_wait<1>();
        __syncthreads();
        compute_stage<4>(sbase + ring_c * BUFB, pA0, pA1, pB, cm);
        if (s + 2 < NSTAGE)
            issue_stage(s + 2, sbase + ring_i * BUFB, sAof, sBof, Arow, Brow);
        else
            cp_commit();     // keep group accounting so wait<1> retires the tail
        ring_c = (ring_c == RING - 1) ? 0 : ring_c + 1;
        ring_i = (ring_i == RING - 1) ? 0 : ring_i + 1;
    }

    // ---- fused LSTM epilogue ----
    // biases depend only on the column: hoist out of the row loops (16 float2
    // loads replace 96 scalar LDGs)
    float gb[4][2][2];   // [gate][nf][q] = bih + bhh
    #pragma unroll
    for (int nf = 0; nf < 2; ++nf) {
        const int col = n0 + wn * 16 + nf * 8 + tig * 2;
        #pragma unroll
        for (int g4 = 0; g4 < 4; ++g4) {
            float2 b1 = __ldg((const float2*)(bih + g4 * 1024 + col));
            float2 b2 = __ldg((const float2*)(bhh + g4 * 1024 + col));
            gb[g4][nf][0] = b1.x + b2.x;
            gb[g4][nf][1] = b1.y + b2.y;
        }
    }
    const size_t cy_base = (size_t)BATCH * HDIM;
    #pragma unroll
    for (int mf = 0; mf < 2; ++mf) {
        #pragma unroll
        for (int i2 = 0; i2 < 2; ++i2) {
            const int row = m0 + wm * 32 + mf * 16 + gid + i2 * 8;
            #pragma unroll
            for (int nf = 0; nf < 2; ++nf) {
                const int col = n0 + wn * 16 + nf * 8 + tig * 2;
                float2 cx2 = __ldg((const float2*)(cx + (size_t)row * HDIM + col));
                float hyv[2], cyv[2];
                #pragma unroll
                for (int q = 0; q < 2; ++q) {
                    const int i = i2 * 2 + q;
                    float gi  = cm[0][mf][nf][i] + gb[0][nf][q];
                    float gf  = cm[1][mf][nf][i] + gb[1][nf][q];
                    float gc  = cm[2][mf][nf][i] + gb[2][nf][q];
                    float go  = cm[3][mf][nf][i] + gb[3][nf][q];
                    float i_  = sigmf(gi);
                    float f_  = sigmf(gf);
                    float c_  = tanhf(gc);
                    float o_  = sigmf(go);
                    float cv  = f_ * ((q == 0) ? cx2.x : cx2.y) + i_ * c_ + p[mf][nf][i];
                    cyv[q] = cv;
                    hyv[q] = o_ * tanhf(cv);
                }
                *(float2*)(out + (size_t)row * HDIM + col)           = make_float2(hyv[0], hyv[1]);
                *(float2*)(out + cy_base + (size_t)row * HDIM + col) = make_float2(cyv[0], cyv[1]);
            }
        }
    }
}

extern "C" void kernel_launch(void* const* d_in, const int* in_sizes, int n_in,
                              void* d_out, int out_size)
{
    (void)in_sizes; (void)n_in; (void)out_size;
    const float* inp  = (const float*)d_in[0];
    const float* hx   = (const float*)d_in[1];
    const float* cx   = (const float*)d_in[2];
    const float* att  = (const float*)d_in[3];
    const float* wih  = (const float*)d_in[4];
    const float* whh  = (const float*)d_in[5];
    const float* bih  = (const float*)d_in[6];
    const float* bhh  = (const float*)d_in[7];
    const float* watt = (const float*)d_in[8];
    const float* batt = (const float*)d_in[9];
    float* out = (float*)d_out;

    dim3 cgrid(1024, 6);
    cvt_all_kernel<<<cgrid, 256>>>((const float4*)att, (const float4*)inp,
                                   (const float4*)hx,  (const float4*)watt,
                                   (const float4*)wih, (const float4*)whh);

    cudaFuncSetAttribute(lstm_att_kernel,
                         cudaFuncAttributeMaxDynamicSharedMemorySize, SMEMB);
    dim3 grid(HDIM / BN, BATCH / BM);
    lstm_att_kernel<<<grid, NTH, SMEMB>>>(cx, bih, bhh, batt, out);
}

// round 17
// speedup vs baseline: 1.0700x; 1.0451x over previous
#include <cuda_runtime.h>
#include <cuda_fp16.h>
#include <cstdint>

#define DI __device__ __forceinline__

static constexpr int HDIM   = 1024;
static constexpr int BATCH  = 8192;
static constexpr int BM     = 64;    // batch rows per CTA
static constexpr int BN     = 32;    // gate cols per CTA
static constexpr int NTH    = 128;   // 4 warps: 2 (m) x 2 (n)
static constexpr int NSTAGE = 48;    // 16 att + 16 input + 16 hx K=64-stages
static constexpr int RING   = 2;     // double buffer -> 48KB -> 4 CTAs/SM

// K=64 fp16 stage buffer: A 64x64 (8KB) + B 4x32x64 (16KB); 128B rows
static constexpr int ABYTES = BM * 128;        // 8192
static constexpr int BUFB   = ABYTES + 16384;  // 24576
static constexpr int SMEMB  = RING * BUFB;     // 49152

// fp16 scratch (u32 element offsets; 2 halves per u32)
static constexpr size_t OFF_ATT  = 0;
static constexpr size_t OFF_INP  = 4194304;
static constexpr size_t OFF_HX   = 8388608;
static constexpr size_t OFF_WATT = 12582912;
static constexpr size_t OFF_WIH  = 13631488;
static constexpr size_t OFF_WHH  = 15728640;
static constexpr size_t CVT_TOTAL = 17825792;   // ~71.3 MB

__device__ uint32_t g_cvt[CVT_TOTAL];

DI float sigmf(float x) { return 1.0f / (1.0f + __expf(-x)); }

DI uint32_t smem_u32(const void* p) {
    uint32_t r;
    asm("{ .reg .u64 t; cvta.to.shared.u64 t, %1; cvt.u32.u64 %0, t; }" : "=r"(r) : "l"(p));
    return r;
}
DI void cp16(uint32_t sdst, const uint32_t* gsrc) {
    asm volatile("cp.async.cg.shared.global [%0], [%1], 16;" :: "r"(sdst), "l"(gsrc));
}
DI void cp_commit() { asm volatile("cp.async.commit_group;" ::: "memory"); }
template <int N>
DI void cp_wait() { asm volatile("cp.async.wait_group %0;" :: "n"(N) : "memory"); }

DI void ldsm4(uint32_t* r, uint32_t addr) {
    asm volatile("ldmatrix.sync.aligned.m8n8.x4.shared.b16 {%0,%1,%2,%3}, [%4];"
                 : "=r"(r[0]), "=r"(r[1]), "=r"(r[2]), "=r"(r[3]) : "r"(addr));
}
DI void mma16(float* d, const uint32_t* a, const uint32_t* b) {
    asm volatile(
        "mma.sync.aligned.m16n8k16.row.col.f32.f16.f16.f32 "
        "{%0,%1,%2,%3}, {%4,%5,%6,%7}, {%8,%9}, {%0,%1,%2,%3};"
        : "+f"(d[0]), "+f"(d[1]), "+f"(d[2]), "+f"(d[3])
        : "r"(a[0]), "r"(a[1]), "r"(a[2]), "r"(a[3]), "r"(b[0]), "r"(b[1]));
}

// ---- prepass: fp32 -> fp16(RN), full-width uint4 stores (6 segments, 1 launch) ----
__global__ void cvt_all_kernel(const float4* s_att, const float4* s_inp, const float4* s_hx,
                               const float4* s_watt, const float4* s_wih, const float4* s_whh)
{
    const int seg = blockIdx.y;
    const float4* src;
    uint4* dst;
    int n16;
    uint32_t* g = g_cvt;
    switch (seg) {
        case 0: src = s_att;  dst = (uint4*)(g + OFF_ATT);  n16 = 1048576; break;
        case 1: src = s_inp;  dst = (uint4*)(g + OFF_INP);  n16 = 1048576; break;
        case 2: src = s_hx;   dst = (uint4*)(g + OFF_HX);   n16 = 1048576; break;
        case 3: src = s_watt; dst = (uint4*)(g + OFF_WATT); n16 = 262144;  break;
        case 4: src = s_wih;  dst = (uint4*)(g + OFF_WIH);  n16 = 524288;  break;
        default: src = s_whh; dst = (uint4*)(g + OFF_WHH);  n16 = 524288;  break;
    }
    int i = blockIdx.x * blockDim.x + threadIdx.x;
    const int stride = gridDim.x * blockDim.x;
    for (; i < n16; i += stride) {
        float4 v0 = __ldg(src + 2 * i);
        float4 v1 = __ldg(src + 2 * i + 1);
        __half2 h0 = __float22half2_rn(make_float2(v0.x, v0.y));
        __half2 h1 = __float22half2_rn(make_float2(v0.z, v0.w));
        __half2 h2 = __float22half2_rn(make_float2(v1.x, v1.y));
        __half2 h3 = __float22half2_rn(make_float2(v1.z, v1.w));
        dst[i] = make_uint4(*(const uint32_t*)&h0, *(const uint32_t*)&h1,
                            *(const uint32_t*)&h2, *(const uint32_t*)&h3);
    }
}

// ---- main kernel ----
// stages 0..15 : A=att,   B=watt (2 att blocks)
// stages 16..31: A=input, B=wih  (4 gate blocks)
// stages 32..47: A=hx,    B=whh  (4 gate blocks)
DI void issue_stage(int s, uint32_t buf, uint32_t sA, uint32_t sB,
                    const uint32_t* Arow, const uint32_t* Brow)
{
    const int seg = s >> 4;
    const int k0  = (s & 15) << 5;                 // u32 offset within 512-u32 row
    const uint32_t bsel = (seg == 0) ? 0u : ((seg == 1) ? 1048576u : 3145728u);
    const uint32_t* Ap = Arow + (size_t)seg * 4194304 + k0;
    const uint32_t* Bp = Brow + bsel + k0;
    const uint32_t dA = buf + sA;
    const uint32_t dB = buf + sB;
    // A: 64 rows, this thread covers rows r0, r0+16, r0+32, r0+48
    cp16(dA,        Ap);
    cp16(dA + 2048, Ap + 8192);
    cp16(dA + 4096, Ap + 16384);
    cp16(dA + 6144, Ap + 24576);
    // B: nb gate blocks x 32 rows; this thread covers rows r0, r0+16 per block
    cp16(dB,        Bp);
    cp16(dB + 2048, Bp + 8192);
    cp16(dB + 4096, Bp + 524288);
    cp16(dB + 6144, Bp + 532480);
    if (seg != 0) {
        cp16(dB + 8192,  Bp + 1048576);
        cp16(dB + 10240, Bp + 1056768);
        cp16(dB + 12288, Bp + 1572864);
        cp16(dB + 14336, Bp + 1581056);
    }
    cp_commit();
}

template <int NB>
DI void compute_stage(uint32_t buf, uint32_t pA0, uint32_t pA1, uint32_t pB,
                      float c[][2][2][4])
{
    const uint32_t aA0 = buf + pA0;
    const uint32_t aA1 = buf + pA1;
    const uint32_t bB  = buf + pB;
    #pragma unroll
    for (int k16 = 0; k16 < 4; ++k16) {
        const uint32_t kx = (uint32_t)(k16 << 5);
        uint32_t a0[4], a1[4];
        ldsm4(a0, aA0 ^ kx);
        ldsm4(a1, aA1 ^ kx);
        #pragma unroll
        for (int blk = 0; blk < NB; ++blk) {
            uint32_t b[4];
            ldsm4(b, (bB + blk * 4096) ^ kx);
            mma16(c[blk][0][0], a0, b);
            mma16(c[blk][0][1], a0, b + 2);
            mma16(c[blk][1][0], a1, b);
            mma16(c[blk][1][1], a1, b + 2);
        }
    }
}

__global__ __launch_bounds__(NTH, 4)
void lstm_att_kernel(const float* __restrict__ cx,
                     const float* __restrict__ bih, const float* __restrict__ bhh,
                     const float* __restrict__ batt,
                     float* __restrict__ out)
{
    extern __shared__ char smem[];
    const int tid  = threadIdx.x;
    const int wid  = tid >> 5;
    const int lane = tid & 31;
    const int wm = wid >> 1, wn = wid & 1;     // 2 x 2 warp grid
    const int n0 = blockIdx.x * BN;
    const int m0 = blockIdx.y * BM;
    const uint32_t sbase = smem_u32(smem);

    // ---- producer addressing (128B rows, chunk ^ row&7 swizzle) ----
    const int r0 = tid >> 3;             // 0..15
    const int cc = tid & 7;              // 16B chunk
    const uint32_t sw   = (uint32_t)((cc ^ (r0 & 7)) << 4);
    const uint32_t sAof = (uint32_t)(r0 * 128) + sw;
    const uint32_t sBof = (uint32_t)ABYTES + (uint32_t)(r0 * 128) + sw;
    const uint32_t* Arow = g_cvt + OFF_ATT  + (size_t)(m0 + r0) * 512 + cc * 4;
    const uint32_t* Brow = g_cvt + OFF_WATT + (size_t)(n0 + r0) * 512 + cc * 4;

    // ---- consumer (ldsm) addressing, XOR-folded ----
    const int arow = wm * 32 + (lane & 15);
    const int ahi  = (lane >> 4) & 1;
    const int ax   = arow & 7;
    const uint32_t pA0 = (uint32_t)(arow * 128)        ^ (uint32_t)(((ahi ^ ax) & 7) << 4);
    const uint32_t pA1 = (uint32_t)((arow + 16) * 128) ^ (uint32_t)(((ahi ^ ax) & 7) << 4);
    const int brow = wn * 16 + (lane & 7) + ((lane & 16) >> 1);
    const int bhi  = (lane >> 3) & 1;
    const int bx   = brow & 7;
    const uint32_t pB  = (uint32_t)ABYTES + ((uint32_t)(brow * 128) ^ (uint32_t)(((bhi ^ bx) & 7) << 4));

    issue_stage(0, sbase, sAof, sBof, Arow, Brow);

    // ===== phase 1: att segment (stages 0..15), 32 accum regs =====
    float ca[2][2][2][4];
    #pragma unroll
    for (int b = 0; b < 2; ++b)
        #pragma unroll
        for (int mf = 0; mf < 2; ++mf)
            #pragma unroll
            for (int nf = 0; nf < 2; ++nf)
                #pragma unroll
                for (int i = 0; i < 4; ++i) ca[b][mf][nf][i] = 0.0f;

    for (int s = 0; s < 16; ++s) {
        cp_wait<0>();          // stage s's group (issued one full stage ago)
        __syncthreads();       // all warps see buf s; all past compute(s-1)
        issue_stage(s + 1, sbase + ((s + 1) & 1) * BUFB, sAof, sBof, Arow, Brow);
        compute_stage<2>(sbase + (s & 1) * BUFB, pA0, pA1, pB, ca);
    }

    // ---- collapse att gates to 16 partials: p = sigmoid(ia) * tanh(aa) ----
    const int gid = lane >> 2, tig = lane & 3;
    float p[2][2][4];
    {
        float bt0[2][2], bt1[2][2];
        #pragma unroll
        for (int nf = 0; nf < 2; ++nf) {
            const int col = n0 + wn * 16 + nf * 8 + tig * 2;
            float2 t0 = __ldg((const float2*)(batt + col));
            float2 t1 = __ldg((const float2*)(batt + 1024 + col));
            bt0[nf][0] = t0.x; bt0[nf][1] = t0.y;
            bt1[nf][0] = t1.x; bt1[nf][1] = t1.y;
        }
        #pragma unroll
        for (int mf = 0; mf < 2; ++mf)
            #pragma unroll
            for (int nf = 0; nf < 2; ++nf)
                #pragma unroll
                for (int i = 0; i < 4; ++i) {
                    const int q = i & 1;
                    float ia = sigmf(ca[0][mf][nf][i] + bt0[nf][q]);
                    float aa = tanhf(ca[1][mf][nf][i] + bt1[nf][q]);
                    p[mf][nf][i] = ia * aa;
                }
    }

    // ===== phase 2: input + hx segments (stages 16..47), 64+16 accum regs =====
    float cm[4][2][2][4];
    #pragma unroll
    for (int b = 0; b < 4; ++b)
        #pragma unroll
        for (int mf = 0; mf < 2; ++mf)
            #pragma unroll
            for (int nf = 0; nf < 2; ++nf)
                #pragma unroll
                for (int i = 0; i < 4; ++i) cm[b][mf][nf][i] = 0.0f;

    for (int s = 16; s < NSTAGE; ++s) {
        cp_wait<0>();
        __syncthreads();
        if (s + 1 < NSTAGE)
            issue_stage(s + 1, sbase + ((s + 1) & 1) * BUFB, sAof, sBof, Arow, Brow);
        compute_stage<4>(sbase + (s & 1) * BUFB, pA0, pA1, pB, cm);
    }

    // ---- fused LSTM epilogue (biases hoisted: column-only dependence) ----
    float gb[4][2][2];   // [gate][nf][q] = bih + bhh
    #pragma unroll
    for (int nf = 0; nf < 2; ++nf) {
        const int col = n0 + wn * 16 + nf * 8 + tig * 2;
        #pragma unroll
        for (int g4 = 0; g4 < 4; ++g4) {
            float2 b1 = __ldg((const float2*)(bih + g4 * 1024 + col));
            float2 b2 = __ldg((const float2*)(bhh + g4 * 1024 + col));
            gb[g4][nf][0] = b1.x + b2.x;
            gb[g4][nf][1] = b1.y + b2.y;
        }
    }
    const size_t cy_base = (size_t)BATCH * HDIM;
    #pragma unroll
    for (int mf = 0; mf < 2; ++mf) {
        #pragma unroll
        for (int i2 = 0; i2 < 2; ++i2) {
            const int row = m0 + wm * 32 + mf * 16 + gid + i2 * 8;
            #pragma unroll
            for (int nf = 0; nf < 2; ++nf) {
                const int col = n0 + wn * 16 + nf * 8 + tig * 2;
                float2 cx2 = __ldg((const float2*)(cx + (size_t)row * HDIM + col));
                float hyv[2], cyv[2];
                #pragma unroll
                for (int q = 0; q < 2; ++q) {
                    const int i = i2 * 2 + q;
                    float gi  = cm[0][mf][nf][i] + gb[0][nf][q];
                    float gf  = cm[1][mf][nf][i] + gb[1][nf][q];
                    float gc  = cm[2][mf][nf][i] + gb[2][nf][q];
                    float go  = cm[3][mf][nf][i] + gb[3][nf][q];
                    float i_  = sigmf(gi);
                    float f_  = sigmf(gf);
                    float c_  = tanhf(gc);
                    float o_  = sigmf(go);
                    float cv  = f_ * ((q == 0) ? cx2.x : cx2.y) + i_ * c_ + p[mf][nf][i];
                    cyv[q] = cv;
                    hyv[q] = o_ * tanhf(cv);
                }
                *(float2*)(out + (size_t)row * HDIM + col)           = make_float2(hyv[0], hyv[1]);
                *(float2*)(out + cy_base + (size_t)row * HDIM + col) = make_float2(cyv[0], cyv[1]);
            }
        }
    }
}

extern "C" void kernel_launch(void* const* d_in, const int* in_sizes, int n_in,
                              void* d_out, int out_size)
{
    (void)in_sizes; (void)n_in; (void)out_size;
    const float* inp  = (const float*)d_in[0];
    const float* hx   = (const float*)d_in[1];
    const float* cx   = (const float*)d_in[2];
    const float* att  = (const float*)d_in[3];
    const float* wih  = (const float*)d_in[4];
    const float* whh  = (const float*)d_in[5];
    const float* bih  = (const float*)d_in[6];
    const float* bhh  = (const float*)d_in[7];
    const float* watt = (const float*)d_in[8];
    const float* batt = (const float*)d_in[9];
    float* out = (float*)d_out;

    dim3 cgrid(1024, 6);
    cvt_all_kernel<<<cgrid, 256>>>((const float4*)att, (const float4*)inp,
                                   (const float4*)hx,  (const float4*)watt,
                                   (const float4*)wih, (const float4*)whh);

    cudaFuncSetAttribute(lstm_att_kernel,
                         cudaFuncAttributeMaxDynamicSharedMemorySize, SMEMB);
    dim3 grid(HDIM / BN, BATCH / BM);   // (32, 128) = 4096 CTAs
    lstm_att_kernel<<<grid, NTH, SMEMB>>>(cx, bih, bhh, batt, out);
}